// round 11
// baseline (speedup 1.0000x reference)
#include <cuda_runtime.h>
#include <cuda_bf16.h>
#include <math.h>
#include <stdint.h>

#define B_ 8
#define P_ 100
#define N_ 50000
#define D_ 128
#define K_ 512
#define CAP 2432
#define SAMPN 2048
#define BUFW 256
#define SELT 512
#define MARGIN 0.25f
#define THRANK 48
#define BAND 0.35f

// Scratch (static device globals — no runtime allocation)
__device__ float g_fastsim[(size_t)B_ * P_ * N_];      // fallback-only
__device__ float g_sample[(size_t)B_ * P_ * SAMPN];    // 6.4 MB (hi*hi approx)
__device__ float g_lof[B_ * P_];                       // float thresholds
__device__ int g_cnt[B_ * P_];
__device__ unsigned long long g_cand[(size_t)B_ * P_ * CAP];  // (key<<32)|n

__device__ __forceinline__ unsigned fkey(float f) {
    unsigned u = __float_as_uint(f);
    return (u & 0x80000000u) ? ~u : (u | 0x80000000u);   // monotonic increasing
}
__device__ __forceinline__ float inv_fkey(unsigned k) {
    return (k & 0x80000000u) ? __uint_as_float(k ^ 0x80000000u)
                             : __uint_as_float(~k);
}

// ---------------------------------------------------------------------------
// GEMM (hi*hi approx): pos @ neg^T tile on mma.sync bf16.
// CTA: 128(m) x 128(n), K=128. 8 warps, 64x32 each. 2 smem tiles (70 KB).
// MODE 0: dense store to g_sample. MODE 1: margin filter + (key,n) append.
// ---------------------------------------------------------------------------
#define TNB 128
#define TSTR 136
#define TILE_BYTES (128 * TSTR * 2)
#define SMEM_TC_BYTES (2 * TILE_BYTES)

__device__ __forceinline__ uint32_t smem_u32(const void* p) {
    return (uint32_t)__cvta_generic_to_shared(p);
}
__device__ __forceinline__ void ldm_x4(uint32_t& r0, uint32_t& r1, uint32_t& r2, uint32_t& r3,
                                       uint32_t addr) {
    asm volatile("ldmatrix.sync.aligned.m8n8.x4.shared.b16 {%0,%1,%2,%3}, [%4];"
                 : "=r"(r0), "=r"(r1), "=r"(r2), "=r"(r3) : "r"(addr));
}
__device__ __forceinline__ void ldm_x2(uint32_t& r0, uint32_t& r1, uint32_t addr) {
    asm volatile("ldmatrix.sync.aligned.m8n8.x2.shared.b16 {%0,%1}, [%2];"
                 : "=r"(r0), "=r"(r1) : "r"(addr));
}
__device__ __forceinline__ void mma16816(float& c0, float& c1, float& c2, float& c3,
                                         uint32_t a0, uint32_t a1, uint32_t a2, uint32_t a3,
                                         uint32_t b0, uint32_t b1) {
    asm volatile("mma.sync.aligned.m16n8k16.row.col.f32.bf16.bf16.f32 "
                 "{%0,%1,%2,%3}, {%4,%5,%6,%7}, {%8,%9}, {%0,%1,%2,%3};"
                 : "+f"(c0), "+f"(c1), "+f"(c2), "+f"(c3)
                 : "r"(a0), "r"(a1), "r"(a2), "r"(a3), "r"(b0), "r"(b1));
}

template <int MODE>
__global__ void __launch_bounds__(256) gemm_kernel(const float* __restrict__ pos,
                                                   const float* __restrict__ neg) {
    extern __shared__ __nv_bfloat16 smem[];
    __nv_bfloat16* Ah = smem;
    __nv_bfloat16* Bh = smem + 128 * TSTR;

    int tid = threadIdx.x;
    int lane = tid & 31;
    int wid = tid >> 5;
    int b = blockIdx.y;
    int n0 = blockIdx.x * TNB;

    const float* Ab = pos + (size_t)b * P_ * D_;
    const float* Bb = neg + (size_t)b * N_ * D_;

    // ---- load + convert (hi only); pad rows / pad n -> zero
#pragma unroll
    for (int i = 0; i < 16; ++i) {
        int f = i * 256 + tid;
        int r = f >> 5;
        int c = (f & 31) << 2;

        float4 va = make_float4(0.f, 0.f, 0.f, 0.f);
        if (r < P_) va = *(const float4*)(Ab + (size_t)r * D_ + c);
        __nv_bfloat162 a0 = __float22bfloat162_rn(make_float2(va.x, va.y));
        __nv_bfloat162 a1 = __float22bfloat162_rn(make_float2(va.z, va.w));
        *(uint2*)(Ah + r * TSTR + c) = make_uint2(*(uint32_t*)&a0, *(uint32_t*)&a1);

        int n = n0 + r;
        float4 vb = make_float4(0.f, 0.f, 0.f, 0.f);
        if (n < N_) vb = *(const float4*)(Bb + (size_t)n * D_ + c);
        __nv_bfloat162 b0 = __float22bfloat162_rn(make_float2(vb.x, vb.y));
        __nv_bfloat162 b1 = __float22bfloat162_rn(make_float2(vb.z, vb.w));
        *(uint2*)(Bh + r * TSTR + c) = make_uint2(*(uint32_t*)&b0, *(uint32_t*)&b1);
    }
    __syncthreads();

    int wm = wid >> 2;
    int wn = wid & 3;
    int mbase = wm * 64;
    int nbase = wn * 32;

    float c[4][4][4];
#pragma unroll
    for (int i = 0; i < 4; ++i)
#pragma unroll
        for (int j = 0; j < 4; ++j)
#pragma unroll
            for (int q = 0; q < 4; ++q) c[i][j][q] = 0.f;

    {
        uint32_t abase = smem_u32(Ah);
        uint32_t bbase = smem_u32(Bh);
        uint32_t aoff = abase + (uint32_t)(lane & 15) * (TSTR * 2) + (uint32_t)(lane >> 4) * 16;
        uint32_t boff = bbase + (uint32_t)(lane & 7) * (TSTR * 2) + (uint32_t)((lane >> 3) & 1) * 16;

#pragma unroll
        for (int kc = 0; kc < 8; ++kc) {
            uint32_t kb = kc * 32;
            uint32_t a0[4], a1[4], a2[4], a3[4];
#pragma unroll
            for (int i = 0; i < 4; ++i)
                ldm_x4(a0[i], a1[i], a2[i], a3[i],
                       aoff + (uint32_t)(mbase + i * 16) * (TSTR * 2) + kb);
            uint32_t b0[4], b1[4];
#pragma unroll
            for (int j = 0; j < 4; ++j)
                ldm_x2(b0[j], b1[j],
                       boff + (uint32_t)(nbase + j * 8) * (TSTR * 2) + kb);
#pragma unroll
            for (int i = 0; i < 4; ++i)
#pragma unroll
                for (int j = 0; j < 4; ++j)
                    mma16816(c[i][j][0], c[i][j][1], c[i][j][2], c[i][j][3],
                             a0[i], a1[i], a2[i], a3[i], b0[j], b1[j]);
        }
    }

    // ---- epilogue
    int mrow0 = mbase + (lane >> 2);
    int ncol0 = n0 + nbase + (lane & 3) * 2;

    if (MODE == 0) {
#pragma unroll
        for (int i = 0; i < 4; ++i) {
            int m0 = mrow0 + i * 16;
            int m1 = m0 + 8;
#pragma unroll
            for (int j = 0; j < 4; ++j) {
                int nc = ncol0 + j * 8;
                if (m0 < P_)
                    *(float2*)(g_sample + (size_t)(b * P_ + m0) * SAMPN + nc) =
                        make_float2(c[i][j][0], c[i][j][1]);
                if (m1 < P_)
                    *(float2*)(g_sample + (size_t)(b * P_ + m1) * SAMPN + nc) =
                        make_float2(c[i][j][2], c[i][j][3]);
            }
        }
    } else {
        __syncthreads();   // tiles dead; reuse smem
        // Words: lof[128] wcnt[8] hist[128] base[128] ovf[2] = 394 -> byte 1576
        // (8-aligned for the uint2 bufs that follow).
        float*    lof    = (float*)smem;            // [128]
        uint32_t* s_wcnt = (uint32_t*)(lof + 128);  // [8]
        uint32_t* s_hist = s_wcnt + 8;              // [128]
        uint32_t* s_base = s_hist + 128;            // [128]
        uint32_t* s_ovf  = s_base + 128;            // [2] (padded for alignment)
        uint2*    bufs   = (uint2*)(s_ovf + 2);     // [8][BUFW], 8B-aligned

        if (tid < 128) {
            lof[tid] = (tid < P_) ? g_lof[b * P_ + tid] : 3.4e38f;
            s_hist[tid] = 0;
        }
        if (tid == 0) *s_ovf = 0;
        __syncthreads();

        // per-warp atomic-free compaction: (key, m|n)
        unsigned wcnt = 0;
        uint2* mybuf = bufs + wid * BUFW;
        unsigned lmask = (1u << lane) - 1u;
#pragma unroll
        for (int i = 0; i < 4; ++i) {
#pragma unroll
            for (int j = 0; j < 4; ++j) {
#pragma unroll
                for (int q = 0; q < 4; ++q) {
                    int m = mrow0 + i * 16 + (q >> 1) * 8;
                    int n = ncol0 + j * 8 + (q & 1);
                    float v = c[i][j][q];
                    bool pred = (m < P_) && (n < N_) && (v >= lof[m & 127]);
                    unsigned msk = __ballot_sync(0xffffffffu, pred);
                    if (pred) {
                        unsigned pos = wcnt + __popc(msk & lmask);
                        if (pos < BUFW)
                            mybuf[pos] = make_uint2(fkey(v), ((unsigned)m << 16) | (unsigned)n);
                    }
                    wcnt += __popc(msk);
                }
            }
        }
        if (lane == 0) {
            s_wcnt[wid] = wcnt > BUFW ? BUFW : wcnt;
            if (wcnt > BUFW) *s_ovf = 1;
        }
        __syncthreads();

        // per-row histogram over all warp segments
#pragma unroll
        for (int w = 0; w < 8; ++w) {
            unsigned cw = s_wcnt[w];
            for (unsigned i = tid; i < cw; i += 256)
                atomicAdd(&s_hist[bufs[w * BUFW + i].y >> 16], 1u);
        }
        __syncthreads();

        // reserve g_cand space: ONE global atomic per row
        unsigned ovf = *s_ovf;
        if (tid < P_) {
            unsigned add = s_hist[tid] + (ovf ? (CAP + 1) : 0);
            s_base[tid] = add ? (unsigned)atomicAdd(&g_cnt[b * P_ + tid], (int)add) : 0u;
            s_hist[tid] = 0;
        }
        __syncthreads();

        // scatter (key<<32 | n)
#pragma unroll
        for (int w = 0; w < 8; ++w) {
            unsigned cw = s_wcnt[w];
            for (unsigned i = tid; i < cw; i += 256) {
                uint2 e = bufs[w * BUFW + i];
                unsigned m = e.y >> 16;
                unsigned off = atomicAdd(&s_hist[m], 1u);
                unsigned pos = s_base[m] + off;
                if (pos < CAP)
                    g_cand[(size_t)(b * P_ + m) * CAP + pos] =
                        ((unsigned long long)e.x << 32) | (e.y & 0xFFFFu);
            }
        }
    }
}

// ---------------------------------------------------------------------------
// shared radix helper
// ---------------------------------------------------------------------------
__device__ void scan_bins(unsigned* hist, unsigned* csum, int nbins, int kr,
                          int sh, unsigned prefix,
                          unsigned* s_thresh, int* s_kr, int tid) {
    int chunks = nbins >> 3;
    if (tid < chunks) {
        unsigned s = 0;
#pragma unroll
        for (int i = 0; i < 8; ++i) s += hist[tid * 8 + i];
        csum[tid] = s;
    }
    __syncthreads();
    if (tid == 0) {
        unsigned cum = 0;
        int c = chunks - 1;
        for (; c > 0; --c) {
            if (cum + csum[c] >= (unsigned)kr) break;
            cum += csum[c];
        }
        int bin = c * 8 + 7;
        for (; bin > c * 8; --bin) {
            if (cum + hist[bin] >= (unsigned)kr) break;
            cum += hist[bin];
        }
        *s_thresh = prefix | ((unsigned)bin << sh);
        *s_kr = kr - (int)cum;
    }
    __syncthreads();
}

__device__ __constant__ int      c_shifts[3] = {21, 10, 0};
__device__ __constant__ unsigned c_masks[3]  = {0x7FFu, 0x7FFu, 0x3FFu};
__device__ __constant__ int      c_nbins[3]  = {2048, 2048, 1024};

// ---------------------------------------------------------------------------
// Threshold kernel: g_lof[row] = (THRANK-th largest of sample) - MARGIN.
// ---------------------------------------------------------------------------
__global__ void __launch_bounds__(256) thresh_kernel() {
    int row = blockIdx.x;
    int tid = threadIdx.x;
    const float* sim = g_sample + (size_t)row * SAMPN;

    __shared__ unsigned hist[2048];
    __shared__ unsigned csum[256];
    __shared__ unsigned s_thresh;
    __shared__ int s_kr;

    unsigned skey[8];
#pragma unroll
    for (int q = 0; q < 2; ++q) {
        float4 v = *(const float4*)(sim + tid * 8 + q * 4);
        skey[q * 4 + 0] = fkey(v.x); skey[q * 4 + 1] = fkey(v.y);
        skey[q * 4 + 2] = fkey(v.z); skey[q * 4 + 3] = fkey(v.w);
    }
    unsigned prefix = 0, pmask = 0;
    int kr = THRANK;
    for (int pass = 0; pass < 3; ++pass) {
        int sh = c_shifts[pass]; unsigned mk = c_masks[pass];
#pragma unroll
        for (int i = 0; i < 8; ++i) hist[tid * 8 + i] = 0;
        __syncthreads();
#pragma unroll
        for (int i = 0; i < 8; ++i) {
            unsigned u = skey[i];
            if ((u & pmask) == prefix) atomicAdd(&hist[(u >> sh) & mk], 1u);
        }
        __syncthreads();
        scan_bins(hist, csum, c_nbins[pass], kr, sh, prefix, &s_thresh, &s_kr, tid);
        prefix = s_thresh; kr = s_kr; pmask |= mk << sh;
        __syncthreads();
    }
    if (tid == 0) {
        g_lof[row] = inv_fkey(prefix) - MARGIN;
        g_cnt[row] = 0;
    }
}

// ---------------------------------------------------------------------------
// Select (512 thr): approx radix -> band filter -> exact fp32 dual dots on
// band (8 candidates/warp/iter for MLP) -> exact top-512 -> softmax agg.
// ---------------------------------------------------------------------------
#define SEL_SMEM ((2048 + 256 + 4 * CAP + 2 * K_ + 2 * 128 + SELT + K_) * 4)

__global__ void __launch_bounds__(SELT) select_kernel(const float* __restrict__ pos,
                                                      const float* __restrict__ neg,
                                                      const float* __restrict__ Wm,
                                                      const float* __restrict__ biasp,
                                                      const float* __restrict__ scalep,
                                                      float* __restrict__ out) {
    int row = blockIdx.x;
    int b = row / P_;
    int tid = threadIdx.x;

    extern __shared__ unsigned dsm[];
    unsigned* hist  = dsm;                  // 2048
    unsigned* csum  = hist + 2048;          // 256
    unsigned* candk = csum + 256;           // CAP  (approx key -> later exact key)
    int*      candn = (int*)(candk + CAP);  // CAP
    int*      bandn = candn + CAP;          // CAP
    float*    bbil  = (float*)(bandn + CAP);// CAP
    int*      sel   = (int*)(bbil + CAP);   // K_
    int*      ties  = sel + K_;             // K_
    float*    ppos  = (float*)(ties + K_);  // 128
    float*    spw   = ppos + 128;           // 128
    float*    red   = spw + 128;            // SELT
    float*    sscore = red + SELT;          // K_

    __shared__ unsigned s_thresh;
    __shared__ int s_kr, s_cntgt, s_cnteq, s_bc;

    if (tid < D_) ppos[tid] = pos[(size_t)row * D_ + tid];
    __syncthreads();
    if (tid < D_) {
        float acc = 0.f;
#pragma unroll 8
        for (int d = 0; d < D_; ++d)
            acc = fmaf(ppos[d], Wm[d * D_ + tid], acc);
        spw[tid] = acc;
    }
    if (tid == 0) s_bc = 0;

    int cnt = g_cnt[row];
    bool fb = (cnt < K_) || (cnt > CAP);

    int lane = tid & 31, wid = tid >> 5;
    int bc = 0;

    if (!fb) {
        for (int i = tid; i < cnt; i += SELT) {
            unsigned long long v = g_cand[(size_t)row * CAP + i];
            candk[i] = (unsigned)(v >> 32);
            candn[i] = (int)(v & 0xFFFFFFFFull);
        }
        __syncthreads();

        // ---- approx radix: 512th-largest approx key
        unsigned prefix = 0, pmask = 0;
        int kr = K_;
        for (int pass = 0; pass < 3; ++pass) {
            int sh = c_shifts[pass]; unsigned mk = c_masks[pass];
            for (int i = tid; i < 2048; i += SELT) hist[i] = 0;
            __syncthreads();
            for (int i = tid; i < cnt; i += SELT) {
                unsigned u = candk[i];
                if ((u & pmask) == prefix) atomicAdd(&hist[(u >> sh) & mk], 1u);
            }
            __syncthreads();
            scan_bins(hist, csum, c_nbins[pass], kr, sh, prefix, &s_thresh, &s_kr, tid);
            prefix = s_thresh; kr = s_kr; pmask |= mk << sh;
            __syncthreads();
        }
        unsigned bandk = fkey(inv_fkey(prefix) - BAND);

        // ---- band filter (ballot-aggregated append)
        int iters = (cnt + SELT - 1) / SELT;
        for (int it = 0; it < iters; ++it) {
            int i = it * SELT + tid;
            bool pred = (i < cnt) && (candk[i] >= bandk);
            unsigned msk = __ballot_sync(0xffffffffu, pred);
            if (msk) {
                int leader = __ffs(msk) - 1;
                unsigned base = 0;
                if (lane == leader) base = atomicAdd((unsigned*)&s_bc, __popc(msk));
                base = __shfl_sync(0xffffffffu, base, leader);
                if (pred)
                    bandn[base + __popc(msk & ((1u << lane) - 1u))] = candn[i];
            }
        }
        __syncthreads();
        bc = s_bc;

        // ---- exact fp32 dual dots on band: 8 candidates/warp/iter (MLP),
        //      each candidate handled by a 16-lane half-warp.
        int sl = lane & 15;
        int half = lane >> 4;
        float4 p0 = ((const float4*)ppos)[sl];
        float4 p1 = ((const float4*)ppos)[sl + 16];
        float4 w0 = ((const float4*)spw)[sl];
        float4 w1 = ((const float4*)spw)[sl + 16];

        for (int base = wid * 8; base < bc; base += 8 * (SELT / 32)) {
            float4 v0[4], v1[4];
            bool valid[4];
#pragma unroll
            for (int u = 0; u < 4; ++u) {
                int cd = base + half + 2 * u;
                valid[u] = (cd < bc);
                if (valid[u]) {
                    int idx = bandn[cd];
                    const float4* vr = (const float4*)(neg + ((size_t)b * N_ + idx) * D_);
                    v0[u] = vr[sl];
                    v1[u] = vr[sl + 16];
                }
            }
#pragma unroll
            for (int u = 0; u < 4; ++u) {
                float sf = 0.f, sb = 0.f;
                if (valid[u]) {
                    sf = v0[u].x * p0.x + v0[u].y * p0.y + v0[u].z * p0.z + v0[u].w * p0.w
                       + v1[u].x * p1.x + v1[u].y * p1.y + v1[u].z * p1.z + v1[u].w * p1.w;
                    sb = v0[u].x * w0.x + v0[u].y * w0.y + v0[u].z * w0.z + v0[u].w * w0.w
                       + v1[u].x * w1.x + v1[u].y * w1.y + v1[u].z * w1.z + v1[u].w * w1.w;
                }
#pragma unroll
                for (int o = 1; o < 16; o <<= 1) {
                    sf += __shfl_xor_sync(0xffffffffu, sf, o);
                    sb += __shfl_xor_sync(0xffffffffu, sb, o);
                }
                if (valid[u] && sl == 0) {
                    int cd = base + half + 2 * u;
                    candk[cd] = fkey(sf);    // candk reused for exact keys
                    bbil[cd] = sb;
                }
            }
        }
    } else {
        __syncthreads();   // ppos ready
        float* simw = g_fastsim + (size_t)row * N_;
        for (int n = tid; n < N_; n += SELT) {
            const float* v = neg + ((size_t)b * N_ + n) * D_;
            float s = 0.f;
#pragma unroll 8
            for (int d = 0; d < D_; ++d) s = fmaf(ppos[d], v[d], s);
            simw[n] = s;
        }
    }
    __syncthreads();

    // ---- exact 512th-largest key -> uth
    unsigned prefix = 0, pmask = 0;
    int kr = K_;
    const float* simr = g_fastsim + (size_t)row * N_;
    for (int pass = 0; pass < 3; ++pass) {
        int sh = c_shifts[pass]; unsigned mk = c_masks[pass];
        for (int i = tid; i < 2048; i += SELT) hist[i] = 0;
        __syncthreads();
        if (!fb) {
            for (int i = tid; i < bc; i += SELT) {
                unsigned u = candk[i];
                if ((u & pmask) == prefix) atomicAdd(&hist[(u >> sh) & mk], 1u);
            }
        } else {
            for (int n = tid; n < N_; n += SELT) {
                unsigned u = fkey(simr[n]);
                if ((u & pmask) == prefix) atomicAdd(&hist[(u >> sh) & mk], 1u);
            }
        }
        __syncthreads();
        scan_bins(hist, csum, c_nbins[pass], kr, sh, prefix, &s_thresh, &s_kr, tid);
        prefix = s_thresh; kr = s_kr; pmask |= mk << sh;
        __syncthreads();
    }
    unsigned uth = prefix;

    // ---- collect winners (> uth) and ties (== uth)
    if (tid == 0) { s_cntgt = 0; s_cnteq = 0; }
    __syncthreads();
    if (!fb) {
        for (int i = tid; i < bc; i += SELT) {
            unsigned u = candk[i];
            if (u > uth) {
                int q = atomicAdd(&s_cntgt, 1);
                sel[q] = i;                      // band index
            } else if (u == uth) {
                int q = atomicAdd(&s_cnteq, 1);
                if (q < K_) ties[q] = i;
            }
        }
    } else {
        for (int n = tid; n < N_; n += SELT) {
            unsigned u = fkey(simr[n]);
            if (u > uth) {
                int q = atomicAdd(&s_cntgt, 1);
                sel[q] = n;                      // direct n index
            } else if (u == uth) {
                int q = atomicAdd(&s_cnteq, 1);
                if (q < K_) ties[q] = n;
            }
        }
    }
    __syncthreads();
    if (tid == 0) {
        int have = s_cntgt;
        int need = K_ - have;
        int te = min(s_cnteq, K_);
        for (int j = 0; j < need; ++j) {
            int bi = -1; long long bv = 0x7fffffffLL;
            for (int t = 0; t < te; ++t) {
                int v = ties[t];
                if (v < 0) continue;
                long long key = fb ? (long long)v : (long long)bandn[v];
                if (key < bv) { bv = key; bi = t; }
            }
            if (bi >= 0) { sel[have + j] = ties[bi]; ties[bi] = -1; }
            else         { sel[have + j] = sel[0]; }
        }
    }
    __syncthreads();

    // ---- scores of the 512 selected
    float biasv = *biasp;
    if (!fb) {
        for (int j = tid; j < K_; j += SELT)
            sscore[j] = bbil[sel[j]] + biasv;
    } else {
        float4 w4l = ((const float4*)spw)[lane];
        for (int s = wid; s < K_; s += SELT / 32) {
            int idx = sel[s];
            float4 v = ((const float4*)(neg + ((size_t)b * N_ + idx) * D_))[lane];
            float sum = v.x * w4l.x + v.y * w4l.y + v.z * w4l.z + v.w * w4l.w;
#pragma unroll
            for (int o = 16; o; o >>= 1)
                sum += __shfl_xor_sync(0xffffffffu, sum, o);
            if (lane == 0) sscore[s] = sum + biasv;
        }
    }
    __syncthreads();

    // ---- softmax aggregation
    float sc;
    {
        float x = *scalep;
        sc = (x > 20.f) ? x : log1pf(expf(x));
    }
    float m = -INFINITY;
    for (int s = tid; s < K_; s += SELT) m = fmaxf(m, sc * sscore[s]);
    red[tid] = m;
    __syncthreads();
    for (int o = SELT / 2; o; o >>= 1) {
        if (tid < o) red[tid] = fmaxf(red[tid], red[tid + o]);
        __syncthreads();
    }
    m = red[0];
    __syncthreads();

    float num = 0.f, den = 0.f;
    for (int s = tid; s < K_; s += SELT) {
        float sv = sscore[s];
        float e = expf(sc * sv - m);
        num = fmaf(e, sv, num);
        den += e;
    }
    red[tid] = num;
    __syncthreads();
    for (int o = SELT / 2; o; o >>= 1) {
        if (tid < o) red[tid] += red[tid + o];
        __syncthreads();
    }
    num = red[0];
    __syncthreads();
    red[tid] = den;
    __syncthreads();
    for (int o = SELT / 2; o; o >>= 1) {
        if (tid < o) red[tid] += red[tid + o];
        __syncthreads();
    }
    den = red[0];

    if (tid == 0) out[row] = num / den;
}

// ---------------------------------------------------------------------------
extern "C" void kernel_launch(void* const* d_in, const int* in_sizes, int n_in,
                              void* d_out, int out_size) {
    const float* fea0  = (const float*)d_in[0];
    const float* neg   = (const float*)d_in[1];
    const float* W     = (const float*)d_in[2];
    const float* bias  = (const float*)d_in[3];
    const float* scale = (const float*)d_in[4];
    float* out = (float*)d_out;

    cudaFuncSetAttribute(gemm_kernel<0>,
                         cudaFuncAttributeMaxDynamicSharedMemorySize, SMEM_TC_BYTES);
    cudaFuncSetAttribute(gemm_kernel<1>,
                         cudaFuncAttributeMaxDynamicSharedMemorySize, SMEM_TC_BYTES);
    cudaFuncSetAttribute(select_kernel,
                         cudaFuncAttributeMaxDynamicSharedMemorySize, SEL_SMEM);

    // 1) sample GEMM: first 2048 columns (hi*hi approx)
    gemm_kernel<0><<<dim3(SAMPN / TNB, B_), 256, SMEM_TC_BYTES>>>(fea0, neg);
    // 2) per-row margin threshold + zero counters
    thresh_kernel<<<B_ * P_, 256>>>();
    // 3) full GEMM with margin filter + (key,n) append
    gemm_kernel<1><<<dim3((N_ + TNB - 1) / TNB, B_), 256, SMEM_TC_BYTES>>>(fea0, neg);
    // 4) band-filtered exact rescore + top-512 + softmax
    select_kernel<<<B_ * P_, SELT, SEL_SMEM>>>(fea0, neg, W, bias, scale, out);
}

// round 12
// speedup vs baseline: 1.4475x; 1.4475x over previous
#include <cuda_runtime.h>
#include <cuda_bf16.h>
#include <math.h>
#include <stdint.h>

#define B_ 8
#define P_ 100
#define N_ 50000
#define D_ 128
#define K_ 512
#define CAP 2432
#define SAMPN 2048
#define BUFW 256
#define SELT 512
#define MARGIN 0.25f
#define THRANK 48
#define BAND 0.35f

// Scratch (static device globals — no runtime allocation)
__device__ float g_fastsim[(size_t)B_ * P_ * N_];      // fallback-only
__device__ float g_sample[(size_t)B_ * P_ * SAMPN];    // 6.4 MB (hi*hi approx)
__device__ float g_lof[B_ * P_];                       // float thresholds
__device__ int g_cnt[B_ * P_];
__device__ unsigned long long g_cand[(size_t)B_ * P_ * CAP];  // (key<<32)|n

__device__ __forceinline__ unsigned fkey(float f) {
    unsigned u = __float_as_uint(f);
    return (u & 0x80000000u) ? ~u : (u | 0x80000000u);   // monotonic increasing
}
__device__ __forceinline__ float inv_fkey(unsigned k) {
    return (k & 0x80000000u) ? __uint_as_float(k ^ 0x80000000u)
                             : __uint_as_float(~k);
}

// ---------------------------------------------------------------------------
// GEMM (hi*hi approx): pos @ neg^T tile on mma.sync bf16.
// CTA: 128(m) x 128(n), K=128. 8 warps, 64x32 each. 2 smem tiles (70 KB).
// MODE 0: dense store to g_sample. MODE 1: margin filter + (key,n) append.
// ---------------------------------------------------------------------------
#define TNB 128
#define TSTR 136
#define TILE_BYTES (128 * TSTR * 2)
#define SMEM_TC_BYTES (2 * TILE_BYTES)

__device__ __forceinline__ uint32_t smem_u32(const void* p) {
    return (uint32_t)__cvta_generic_to_shared(p);
}
__device__ __forceinline__ void ldm_x4(uint32_t& r0, uint32_t& r1, uint32_t& r2, uint32_t& r3,
                                       uint32_t addr) {
    asm volatile("ldmatrix.sync.aligned.m8n8.x4.shared.b16 {%0,%1,%2,%3}, [%4];"
                 : "=r"(r0), "=r"(r1), "=r"(r2), "=r"(r3) : "r"(addr));
}
__device__ __forceinline__ void ldm_x2(uint32_t& r0, uint32_t& r1, uint32_t addr) {
    asm volatile("ldmatrix.sync.aligned.m8n8.x2.shared.b16 {%0,%1}, [%2];"
                 : "=r"(r0), "=r"(r1) : "r"(addr));
}
__device__ __forceinline__ void mma16816(float& c0, float& c1, float& c2, float& c3,
                                         uint32_t a0, uint32_t a1, uint32_t a2, uint32_t a3,
                                         uint32_t b0, uint32_t b1) {
    asm volatile("mma.sync.aligned.m16n8k16.row.col.f32.bf16.bf16.f32 "
                 "{%0,%1,%2,%3}, {%4,%5,%6,%7}, {%8,%9}, {%0,%1,%2,%3};"
                 : "+f"(c0), "+f"(c1), "+f"(c2), "+f"(c3)
                 : "r"(a0), "r"(a1), "r"(a2), "r"(a3), "r"(b0), "r"(b1));
}

template <int MODE>
__global__ void __launch_bounds__(256) gemm_kernel(const float* __restrict__ pos,
                                                   const float* __restrict__ neg) {
    extern __shared__ __nv_bfloat16 smem[];
    __nv_bfloat16* Ah = smem;
    __nv_bfloat16* Bh = smem + 128 * TSTR;

    int tid = threadIdx.x;
    int lane = tid & 31;
    int wid = tid >> 5;
    int b = blockIdx.y;
    int n0 = blockIdx.x * TNB;

    const float* Ab = pos + (size_t)b * P_ * D_;
    const float* Bb = neg + (size_t)b * N_ * D_;

    // ---- load + convert (hi only); pad rows / pad n -> zero
#pragma unroll
    for (int i = 0; i < 16; ++i) {
        int f = i * 256 + tid;
        int r = f >> 5;
        int c = (f & 31) << 2;

        float4 va = make_float4(0.f, 0.f, 0.f, 0.f);
        if (r < P_) va = *(const float4*)(Ab + (size_t)r * D_ + c);
        __nv_bfloat162 a0 = __float22bfloat162_rn(make_float2(va.x, va.y));
        __nv_bfloat162 a1 = __float22bfloat162_rn(make_float2(va.z, va.w));
        *(uint2*)(Ah + r * TSTR + c) = make_uint2(*(uint32_t*)&a0, *(uint32_t*)&a1);

        int n = n0 + r;
        float4 vb = make_float4(0.f, 0.f, 0.f, 0.f);
        if (n < N_) vb = *(const float4*)(Bb + (size_t)n * D_ + c);
        __nv_bfloat162 b0 = __float22bfloat162_rn(make_float2(vb.x, vb.y));
        __nv_bfloat162 b1 = __float22bfloat162_rn(make_float2(vb.z, vb.w));
        *(uint2*)(Bh + r * TSTR + c) = make_uint2(*(uint32_t*)&b0, *(uint32_t*)&b1);
    }
    __syncthreads();

    int wm = wid >> 2;
    int wn = wid & 3;
    int mbase = wm * 64;
    int nbase = wn * 32;

    float c[4][4][4];
#pragma unroll
    for (int i = 0; i < 4; ++i)
#pragma unroll
        for (int j = 0; j < 4; ++j)
#pragma unroll
            for (int q = 0; q < 4; ++q) c[i][j][q] = 0.f;

    {
        uint32_t abase = smem_u32(Ah);
        uint32_t bbase = smem_u32(Bh);
        uint32_t aoff = abase + (uint32_t)(lane & 15) * (TSTR * 2) + (uint32_t)(lane >> 4) * 16;
        uint32_t boff = bbase + (uint32_t)(lane & 7) * (TSTR * 2) + (uint32_t)((lane >> 3) & 1) * 16;

#pragma unroll
        for (int kc = 0; kc < 8; ++kc) {
            uint32_t kb = kc * 32;
            uint32_t a0[4], a1[4], a2[4], a3[4];
#pragma unroll
            for (int i = 0; i < 4; ++i)
                ldm_x4(a0[i], a1[i], a2[i], a3[i],
                       aoff + (uint32_t)(mbase + i * 16) * (TSTR * 2) + kb);
            uint32_t b0[4], b1[4];
#pragma unroll
            for (int j = 0; j < 4; ++j)
                ldm_x2(b0[j], b1[j],
                       boff + (uint32_t)(nbase + j * 8) * (TSTR * 2) + kb);
#pragma unroll
            for (int i = 0; i < 4; ++i)
#pragma unroll
                for (int j = 0; j < 4; ++j)
                    mma16816(c[i][j][0], c[i][j][1], c[i][j][2], c[i][j][3],
                             a0[i], a1[i], a2[i], a3[i], b0[j], b1[j]);
        }
    }

    // ---- epilogue
    int mrow0 = mbase + (lane >> 2);
    int ncol0 = n0 + nbase + (lane & 3) * 2;

    if (MODE == 0) {
#pragma unroll
        for (int i = 0; i < 4; ++i) {
            int m0 = mrow0 + i * 16;
            int m1 = m0 + 8;
#pragma unroll
            for (int j = 0; j < 4; ++j) {
                int nc = ncol0 + j * 8;
                if (m0 < P_)
                    *(float2*)(g_sample + (size_t)(b * P_ + m0) * SAMPN + nc) =
                        make_float2(c[i][j][0], c[i][j][1]);
                if (m1 < P_)
                    *(float2*)(g_sample + (size_t)(b * P_ + m1) * SAMPN + nc) =
                        make_float2(c[i][j][2], c[i][j][3]);
            }
        }
    } else {
        __syncthreads();   // tiles dead; reuse smem
        // Words: lof[128] wcnt[8] hist[128] base[128] ovf[2] = 394 -> byte 1576
        // (8-aligned for the uint2 bufs that follow).
        float*    lof    = (float*)smem;            // [128]
        uint32_t* s_wcnt = (uint32_t*)(lof + 128);  // [8]
        uint32_t* s_hist = s_wcnt + 8;              // [128]
        uint32_t* s_base = s_hist + 128;            // [128]
        uint32_t* s_ovf  = s_base + 128;            // [2] (padded for alignment)
        uint2*    bufs   = (uint2*)(s_ovf + 2);     // [8][BUFW], 8B-aligned

        if (tid < 128) {
            lof[tid] = (tid < P_) ? g_lof[b * P_ + tid] : 3.4e38f;
            s_hist[tid] = 0;
        }
        if (tid == 0) *s_ovf = 0;
        __syncthreads();

        // per-warp atomic-free compaction: (key, m|n)
        unsigned wcnt = 0;
        uint2* mybuf = bufs + wid * BUFW;
        unsigned lmask = (1u << lane) - 1u;
#pragma unroll
        for (int i = 0; i < 4; ++i) {
#pragma unroll
            for (int j = 0; j < 4; ++j) {
#pragma unroll
                for (int q = 0; q < 4; ++q) {
                    int m = mrow0 + i * 16 + (q >> 1) * 8;
                    int n = ncol0 + j * 8 + (q & 1);
                    float v = c[i][j][q];
                    bool pred = (m < P_) && (n < N_) && (v >= lof[m & 127]);
                    unsigned msk = __ballot_sync(0xffffffffu, pred);
                    if (pred) {
                        unsigned pos = wcnt + __popc(msk & lmask);
                        if (pos < BUFW)
                            mybuf[pos] = make_uint2(fkey(v), ((unsigned)m << 16) | (unsigned)n);
                    }
                    wcnt += __popc(msk);
                }
            }
        }
        if (lane == 0) {
            s_wcnt[wid] = wcnt > BUFW ? BUFW : wcnt;
            if (wcnt > BUFW) *s_ovf = 1;
        }
        __syncthreads();

        // per-row histogram over all warp segments
#pragma unroll
        for (int w = 0; w < 8; ++w) {
            unsigned cw = s_wcnt[w];
            for (unsigned i = tid; i < cw; i += 256)
                atomicAdd(&s_hist[bufs[w * BUFW + i].y >> 16], 1u);
        }
        __syncthreads();

        // reserve g_cand space: ONE global atomic per row
        unsigned ovf = *s_ovf;
        if (tid < P_) {
            unsigned add = s_hist[tid] + (ovf ? (CAP + 1) : 0);
            s_base[tid] = add ? (unsigned)atomicAdd(&g_cnt[b * P_ + tid], (int)add) : 0u;
            s_hist[tid] = 0;
        }
        __syncthreads();

        // scatter (key<<32 | n)
#pragma unroll
        for (int w = 0; w < 8; ++w) {
            unsigned cw = s_wcnt[w];
            for (unsigned i = tid; i < cw; i += 256) {
                uint2 e = bufs[w * BUFW + i];
                unsigned m = e.y >> 16;
                unsigned off = atomicAdd(&s_hist[m], 1u);
                unsigned pos = s_base[m] + off;
                if (pos < CAP)
                    g_cand[(size_t)(b * P_ + m) * CAP + pos] =
                        ((unsigned long long)e.x << 32) | (e.y & 0xFFFFu);
            }
        }
    }
}

// ---------------------------------------------------------------------------
// shared radix helper
// ---------------------------------------------------------------------------
__device__ void scan_bins(unsigned* hist, unsigned* csum, int nbins, int kr,
                          int sh, unsigned prefix,
                          unsigned* s_thresh, int* s_kr, int tid) {
    int chunks = nbins >> 3;
    if (tid < chunks) {
        unsigned s = 0;
#pragma unroll
        for (int i = 0; i < 8; ++i) s += hist[tid * 8 + i];
        csum[tid] = s;
    }
    __syncthreads();
    if (tid == 0) {
        unsigned cum = 0;
        int c = chunks - 1;
        for (; c > 0; --c) {
            if (cum + csum[c] >= (unsigned)kr) break;
            cum += csum[c];
        }
        int bin = c * 8 + 7;
        for (; bin > c * 8; --bin) {
            if (cum + hist[bin] >= (unsigned)kr) break;
            cum += hist[bin];
        }
        *s_thresh = prefix | ((unsigned)bin << sh);
        *s_kr = kr - (int)cum;
    }
    __syncthreads();
}

__device__ __constant__ int      c_shifts[3] = {21, 10, 0};
__device__ __constant__ unsigned c_masks[3]  = {0x7FFu, 0x7FFu, 0x3FFu};
__device__ __constant__ int      c_nbins[3]  = {2048, 2048, 1024};

// ---------------------------------------------------------------------------
// Threshold kernel: g_lof[row] = (THRANK-th largest of sample) - MARGIN.
// ---------------------------------------------------------------------------
__global__ void __launch_bounds__(256) thresh_kernel() {
    int row = blockIdx.x;
    int tid = threadIdx.x;
    const float* sim = g_sample + (size_t)row * SAMPN;

    __shared__ unsigned hist[2048];
    __shared__ unsigned csum[256];
    __shared__ unsigned s_thresh;
    __shared__ int s_kr;

    unsigned skey[8];
#pragma unroll
    for (int q = 0; q < 2; ++q) {
        float4 v = *(const float4*)(sim + tid * 8 + q * 4);
        skey[q * 4 + 0] = fkey(v.x); skey[q * 4 + 1] = fkey(v.y);
        skey[q * 4 + 2] = fkey(v.z); skey[q * 4 + 3] = fkey(v.w);
    }
    unsigned prefix = 0, pmask = 0;
    int kr = THRANK;
    for (int pass = 0; pass < 3; ++pass) {
        int sh = c_shifts[pass]; unsigned mk = c_masks[pass];
#pragma unroll
        for (int i = 0; i < 8; ++i) hist[tid * 8 + i] = 0;
        __syncthreads();
#pragma unroll
        for (int i = 0; i < 8; ++i) {
            unsigned u = skey[i];
            if ((u & pmask) == prefix) atomicAdd(&hist[(u >> sh) & mk], 1u);
        }
        __syncthreads();
        scan_bins(hist, csum, c_nbins[pass], kr, sh, prefix, &s_thresh, &s_kr, tid);
        prefix = s_thresh; kr = s_kr; pmask |= mk << sh;
        __syncthreads();
    }
    if (tid == 0) {
        g_lof[row] = inv_fkey(prefix) - MARGIN;
        g_cnt[row] = 0;
    }
}

// ---------------------------------------------------------------------------
// Select (512 thr): approx radix -> band filter -> exact fp32 dual dots on
// band (2 candidates/warp, 16 lanes each — the R10 shape) -> top-512 -> agg.
// ---------------------------------------------------------------------------
#define SEL_SMEM ((2048 + 256 + 4 * CAP + 2 * K_ + 2 * 128 + SELT + K_) * 4)

__global__ void __launch_bounds__(SELT) select_kernel(const float* __restrict__ pos,
                                                      const float* __restrict__ neg,
                                                      const float* __restrict__ Wm,
                                                      const float* __restrict__ biasp,
                                                      const float* __restrict__ scalep,
                                                      float* __restrict__ out) {
    int row = blockIdx.x;
    int b = row / P_;
    int tid = threadIdx.x;

    extern __shared__ unsigned dsm[];
    unsigned* hist  = dsm;                  // 2048
    unsigned* csum  = hist + 2048;          // 256
    unsigned* candk = csum + 256;           // CAP  (approx key -> later exact key)
    int*      candn = (int*)(candk + CAP);  // CAP
    int*      bandn = candn + CAP;          // CAP
    float*    bbil  = (float*)(bandn + CAP);// CAP
    int*      sel   = (int*)(bbil + CAP);   // K_
    int*      ties  = sel + K_;             // K_
    float*    ppos  = (float*)(ties + K_);  // 128
    float*    spw   = ppos + 128;           // 128
    float*    red   = spw + 128;            // SELT
    float*    sscore = red + SELT;          // K_

    __shared__ unsigned s_thresh;
    __shared__ int s_kr, s_cntgt, s_cnteq, s_bc;

    if (tid < D_) ppos[tid] = pos[(size_t)row * D_ + tid];
    __syncthreads();
    if (tid < D_) {
        float acc = 0.f;
#pragma unroll 8
        for (int d = 0; d < D_; ++d)
            acc = fmaf(ppos[d], Wm[d * D_ + tid], acc);
        spw[tid] = acc;
    }
    if (tid == 0) s_bc = 0;

    int cnt = g_cnt[row];
    bool fb = (cnt < K_) || (cnt > CAP);

    int lane = tid & 31, wid = tid >> 5;
    int bc = 0;

    if (!fb) {
        for (int i = tid; i < cnt; i += SELT) {
            unsigned long long v = g_cand[(size_t)row * CAP + i];
            candk[i] = (unsigned)(v >> 32);
            candn[i] = (int)(v & 0xFFFFFFFFull);
        }
        __syncthreads();

        // ---- approx radix: 512th-largest approx key
        unsigned prefix = 0, pmask = 0;
        int kr = K_;
        for (int pass = 0; pass < 3; ++pass) {
            int sh = c_shifts[pass]; unsigned mk = c_masks[pass];
            for (int i = tid; i < 2048; i += SELT) hist[i] = 0;
            __syncthreads();
            for (int i = tid; i < cnt; i += SELT) {
                unsigned u = candk[i];
                if ((u & pmask) == prefix) atomicAdd(&hist[(u >> sh) & mk], 1u);
            }
            __syncthreads();
            scan_bins(hist, csum, c_nbins[pass], kr, sh, prefix, &s_thresh, &s_kr, tid);
            prefix = s_thresh; kr = s_kr; pmask |= mk << sh;
            __syncthreads();
        }
        unsigned bandk = fkey(inv_fkey(prefix) - BAND);

        // ---- band filter (ballot-aggregated append)
        int iters = (cnt + SELT - 1) / SELT;
        for (int it = 0; it < iters; ++it) {
            int i = it * SELT + tid;
            bool pred = (i < cnt) && (candk[i] >= bandk);
            unsigned msk = __ballot_sync(0xffffffffu, pred);
            if (msk) {
                int leader = __ffs(msk) - 1;
                unsigned base = 0;
                if (lane == leader) base = atomicAdd((unsigned*)&s_bc, __popc(msk));
                base = __shfl_sync(0xffffffffu, base, leader);
                if (pred)
                    bandn[base + __popc(msk & ((1u << lane) - 1u))] = candn[i];
            }
        }
        __syncthreads();
        bc = s_bc;

        // ---- exact fp32 dual dots on band: 2 candidates/warp, 16 lanes each
        int sl = lane & 15;
        int half = lane >> 4;
        float4 p0 = ((const float4*)ppos)[sl];
        float4 p1 = ((const float4*)ppos)[sl + 16];
        float4 w0 = ((const float4*)spw)[sl];
        float4 w1 = ((const float4*)spw)[sl + 16];

        for (int cd0 = wid * 2; cd0 < bc; cd0 += 2 * (SELT / 32)) {
            int cd = cd0 + half;
            bool valid = (cd < bc);
            float sf = 0.f, sb = 0.f;
            if (valid) {
                int idx = bandn[cd];
                const float4* vr = (const float4*)(neg + ((size_t)b * N_ + idx) * D_);
                float4 v0 = vr[sl];
                float4 v1 = vr[sl + 16];
                sf = v0.x * p0.x + v0.y * p0.y + v0.z * p0.z + v0.w * p0.w
                   + v1.x * p1.x + v1.y * p1.y + v1.z * p1.z + v1.w * p1.w;
                sb = v0.x * w0.x + v0.y * w0.y + v0.z * w0.z + v0.w * w0.w
                   + v1.x * w1.x + v1.y * w1.y + v1.z * w1.z + v1.w * w1.w;
            }
#pragma unroll
            for (int o = 1; o < 16; o <<= 1) {
                sf += __shfl_xor_sync(0xffffffffu, sf, o);
                sb += __shfl_xor_sync(0xffffffffu, sb, o);
            }
            if (valid && sl == 0) {
                candk[cd] = fkey(sf);    // candk reused for exact keys
                bbil[cd] = sb;
            }
        }
    } else {
        __syncthreads();   // ppos ready
        float* simw = g_fastsim + (size_t)row * N_;
        for (int n = tid; n < N_; n += SELT) {
            const float* v = neg + ((size_t)b * N_ + n) * D_;
            float s = 0.f;
#pragma unroll 8
            for (int d = 0; d < D_; ++d) s = fmaf(ppos[d], v[d], s);
            simw[n] = s;
        }
    }
    __syncthreads();

    // ---- exact 512th-largest key -> uth
    unsigned prefix = 0, pmask = 0;
    int kr = K_;
    const float* simr = g_fastsim + (size_t)row * N_;
    for (int pass = 0; pass < 3; ++pass) {
        int sh = c_shifts[pass]; unsigned mk = c_masks[pass];
        for (int i = tid; i < 2048; i += SELT) hist[i] = 0;
        __syncthreads();
        if (!fb) {
            for (int i = tid; i < bc; i += SELT) {
                unsigned u = candk[i];
                if ((u & pmask) == prefix) atomicAdd(&hist[(u >> sh) & mk], 1u);
            }
        } else {
            for (int n = tid; n < N_; n += SELT) {
                unsigned u = fkey(simr[n]);
                if ((u & pmask) == prefix) atomicAdd(&hist[(u >> sh) & mk], 1u);
            }
        }
        __syncthreads();
        scan_bins(hist, csum, c_nbins[pass], kr, sh, prefix, &s_thresh, &s_kr, tid);
        prefix = s_thresh; kr = s_kr; pmask |= mk << sh;
        __syncthreads();
    }
    unsigned uth = prefix;

    // ---- collect winners (> uth) and ties (== uth)
    if (tid == 0) { s_cntgt = 0; s_cnteq = 0; }
    __syncthreads();
    if (!fb) {
        for (int i = tid; i < bc; i += SELT) {
            unsigned u = candk[i];
            if (u > uth) {
                int q = atomicAdd(&s_cntgt, 1);
                sel[q] = i;                      // band index
            } else if (u == uth) {
                int q = atomicAdd(&s_cnteq, 1);
                if (q < K_) ties[q] = i;
            }
        }
    } else {
        for (int n = tid; n < N_; n += SELT) {
            unsigned u = fkey(simr[n]);
            if (u > uth) {
                int q = atomicAdd(&s_cntgt, 1);
                sel[q] = n;                      // direct n index
            } else if (u == uth) {
                int q = atomicAdd(&s_cnteq, 1);
                if (q < K_) ties[q] = n;
            }
        }
    }
    __syncthreads();
    if (tid == 0) {
        int have = s_cntgt;
        int need = K_ - have;
        int te = min(s_cnteq, K_);
        for (int j = 0; j < need; ++j) {
            int bi = -1; long long bv = 0x7fffffffLL;
            for (int t = 0; t < te; ++t) {
                int v = ties[t];
                if (v < 0) continue;
                long long key = fb ? (long long)v : (long long)bandn[v];
                if (key < bv) { bv = key; bi = t; }
            }
            if (bi >= 0) { sel[have + j] = ties[bi]; ties[bi] = -1; }
            else         { sel[have + j] = sel[0]; }
        }
    }
    __syncthreads();

    // ---- scores of the 512 selected
    float biasv = *biasp;
    if (!fb) {
        for (int j = tid; j < K_; j += SELT)
            sscore[j] = bbil[sel[j]] + biasv;
    } else {
        float4 w4l = ((const float4*)spw)[lane];
        for (int s = wid; s < K_; s += SELT / 32) {
            int idx = sel[s];
            float4 v = ((const float4*)(neg + ((size_t)b * N_ + idx) * D_))[lane];
            float sum = v.x * w4l.x + v.y * w4l.y + v.z * w4l.z + v.w * w4l.w;
#pragma unroll
            for (int o = 16; o; o >>= 1)
                sum += __shfl_xor_sync(0xffffffffu, sum, o);
            if (lane == 0) sscore[s] = sum + biasv;
        }
    }
    __syncthreads();

    // ---- softmax aggregation
    float sc;
    {
        float x = *scalep;
        sc = (x > 20.f) ? x : log1pf(expf(x));
    }
    float m = -INFINITY;
    for (int s = tid; s < K_; s += SELT) m = fmaxf(m, sc * sscore[s]);
    red[tid] = m;
    __syncthreads();
    for (int o = SELT / 2; o; o >>= 1) {
        if (tid < o) red[tid] = fmaxf(red[tid], red[tid + o]);
        __syncthreads();
    }
    m = red[0];
    __syncthreads();

    float num = 0.f, den = 0.f;
    for (int s = tid; s < K_; s += SELT) {
        float sv = sscore[s];
        float e = expf(sc * sv - m);
        num = fmaf(e, sv, num);
        den += e;
    }
    red[tid] = num;
    __syncthreads();
    for (int o = SELT / 2; o; o >>= 1) {
        if (tid < o) red[tid] += red[tid + o];
        __syncthreads();
    }
    num = red[0];
    __syncthreads();
    red[tid] = den;
    __syncthreads();
    for (int o = SELT / 2; o; o >>= 1) {
        if (tid < o) red[tid] += red[tid + o];
        __syncthreads();
    }
    den = red[0];

    if (tid == 0) out[row] = num / den;
}

// ---------------------------------------------------------------------------
extern "C" void kernel_launch(void* const* d_in, const int* in_sizes, int n_in,
                              void* d_out, int out_size) {
    const float* fea0  = (const float*)d_in[0];
    const float* neg   = (const float*)d_in[1];
    const float* W     = (const float*)d_in[2];
    const float* bias  = (const float*)d_in[3];
    const float* scale = (const float*)d_in[4];
    float* out = (float*)d_out;

    cudaFuncSetAttribute(gemm_kernel<0>,
                         cudaFuncAttributeMaxDynamicSharedMemorySize, SMEM_TC_BYTES);
    cudaFuncSetAttribute(gemm_kernel<1>,
                         cudaFuncAttributeMaxDynamicSharedMemorySize, SMEM_TC_BYTES);
    cudaFuncSetAttribute(select_kernel,
                         cudaFuncAttributeMaxDynamicSharedMemorySize, SEL_SMEM);

    // 1) sample GEMM: first 2048 columns (hi*hi approx)
    gemm_kernel<0><<<dim3(SAMPN / TNB, B_), 256, SMEM_TC_BYTES>>>(fea0, neg);
    // 2) per-row margin threshold + zero counters
    thresh_kernel<<<B_ * P_, 256>>>();
    // 3) full GEMM with margin filter + (key,n) append
    gemm_kernel<1><<<dim3((N_ + TNB - 1) / TNB, B_), 256, SMEM_TC_BYTES>>>(fea0, neg);
    // 4) band-filtered exact rescore + top-512 + softmax
    select_kernel<<<B_ * P_, SELT, SEL_SMEM>>>(fea0, neg, W, bias, scale, out);
}